// round 6
// baseline (speedup 1.0000x reference)
#include <cuda_runtime.h>
#include <math_constants.h>

// TropicalLinear forward: out[n,o] = max_j( x[n,j] + w[o,j] ) + bias[o]
//
// 128 blocks x 512 threads (16 warps/SM = 4/SMSP), tile BM=64 x BO=16.
// 2 outputs/thread (rows ty, ty+32; col tx). Double-buffered smem, BK=64.
// Padded smem rows (68 floats = 17 x 16B granules): conflict-free LDS with
// pure immediate-offset addressing (no per-access XOR -> no alu-pipe pollution).

#define N_DIM   128
#define IN_DIM  1024
#define OUT_DIM 1024
#define BM      64
#define BO      16
#define BK      64
#define NITER   (IN_DIM / BK)   // 16
#define XSTR    68              // floats per smem row (17 granules, odd -> conflict-free)

__global__ __launch_bounds__(512, 1)
void tropical_kernel(const float* __restrict__ x,
                     const float* __restrict__ w,
                     const float* __restrict__ bias,
                     float* __restrict__ out)
{
    __shared__ float xs[2][BM * XSTR];   // 2 * 64*68*4 = 34816 B
    __shared__ float ws[2][BO * XSTR];   // 2 * 16*68*4 =  8704 B

    const int t  = threadIdx.x;
    const int tx = t & 15;        // o col within tile
    const int ty = t >> 4;        // 0..31: x rows ty, ty+32
    const int oBase = blockIdx.x * BO;
    const int nBase = blockIdx.y * BM;

    // loaders: every thread stages 2 x-granules (rows ty, ty+32, slot tx);
    // threads t<256 also stage 1 w-granule (row ty = t>>4 in 0..15, slot tx)
    const bool wload = (t < 256);
    const float* xg0 = x + (nBase + ty) * IN_DIM + (tx << 2);
    const float* xg1 = xg0 + 32 * IN_DIM;
    const float* wg  = w + (oBase + ty) * IN_DIM + (tx << 2);

    float acc0 = -CUDART_INF_F;
    float acc1 = -CUDART_INF_F;

    float4 xr0, xr1, wr = make_float4(0.f, 0.f, 0.f, 0.f);

    // ---- prologue: tile 0 -> buffer 0 ----
    xr0 = *(const float4*)xg0;
    xr1 = *(const float4*)xg1;
    if (wload) wr = *(const float4*)wg;
    *(float4*)&xs[0][ty * XSTR + (tx << 2)]        = xr0;
    *(float4*)&xs[0][(ty + 32) * XSTR + (tx << 2)] = xr1;
    if (wload) *(float4*)&ws[0][ty * XSTR + (tx << 2)] = wr;
    __syncthreads();

#pragma unroll 1
    for (int i = 0; i < NITER - 1; i++) {
        const int b = i & 1;

        // prefetch next tile (gmem latency hidden under compute)
        xr0 = *(const float4*)(xg0 + (i + 1) * BK);
        xr1 = *(const float4*)(xg1 + (i + 1) * BK);
        if (wload) wr = *(const float4*)(wg + (i + 1) * BK);

        // compute on buffer b: all LDS at immediate offsets from 3 base ptrs
        const float* px0 = &xs[b][ty * XSTR];
        const float* px1 = &xs[b][(ty + 32) * XSTR];
        const float* pw  = &ws[b][tx * XSTR];
#pragma unroll
        for (int k4 = 0; k4 < BK / 4; k4++) {
            const float4 a0 = *(const float4*)(px0 + (k4 << 2));
            const float4 a1 = *(const float4*)(px1 + (k4 << 2));
            const float4 bw = *(const float4*)(pw  + (k4 << 2));
            acc0 = fmaxf(acc0, a0.x + bw.x); acc0 = fmaxf(acc0, a0.y + bw.y);
            acc0 = fmaxf(acc0, a0.z + bw.z); acc0 = fmaxf(acc0, a0.w + bw.w);
            acc1 = fmaxf(acc1, a1.x + bw.x); acc1 = fmaxf(acc1, a1.y + bw.y);
            acc1 = fmaxf(acc1, a1.z + bw.z); acc1 = fmaxf(acc1, a1.w + bw.w);
        }

        // stage prefetched tile into the other buffer
        const int nb = b ^ 1;
        *(float4*)&xs[nb][ty * XSTR + (tx << 2)]        = xr0;
        *(float4*)&xs[nb][(ty + 32) * XSTR + (tx << 2)] = xr1;
        if (wload) *(float4*)&ws[nb][ty * XSTR + (tx << 2)] = wr;
        __syncthreads();
    }

    // ---- final tile (buffer 1) ----
    {
        const int b = (NITER - 1) & 1;
        const float* px0 = &xs[b][ty * XSTR];
        const float* px1 = &xs[b][(ty + 32) * XSTR];
        const float* pw  = &ws[b][tx * XSTR];
#pragma unroll
        for (int k4 = 0; k4 < BK / 4; k4++) {
            const float4 a0 = *(const float4*)(px0 + (k4 << 2));
            const float4 a1 = *(const float4*)(px1 + (k4 << 2));
            const float4 bw = *(const float4*)(pw  + (k4 << 2));
            acc0 = fmaxf(acc0, a0.x + bw.x); acc0 = fmaxf(acc0, a0.y + bw.y);
            acc0 = fmaxf(acc0, a0.z + bw.z); acc0 = fmaxf(acc0, a0.w + bw.w);
            acc1 = fmaxf(acc1, a1.x + bw.x); acc1 = fmaxf(acc1, a1.y + bw.y);
            acc1 = fmaxf(acc1, a1.z + bw.z); acc1 = fmaxf(acc1, a1.w + bw.w);
        }
    }

    // ---- epilogue ----
    const int o  = oBase + tx;
    const float bv = bias[o];
    out[(nBase + ty) * OUT_DIM + o]        = acc0 + bv;
    out[(nBase + ty + 32) * OUT_DIM + o]   = acc1 + bv;
}

extern "C" void kernel_launch(void* const* d_in, const int* in_sizes, int n_in,
                              void* d_out, int out_size)
{
    const float* x    = (const float*)d_in[0];   // [128, 1024]
    const float* w    = (const float*)d_in[1];   // [1024, 1024]
    const float* bias = (const float*)d_in[2];   // [1024]
    float* out = (float*)d_out;                  // [128, 1024]

    dim3 grid(OUT_DIM / BO, N_DIM / BM);         // 64 x 2 = 128 blocks
    tropical_kernel<<<grid, 512>>>(x, w, bias, out);
}